// round 2
// baseline (speedup 1.0000x reference)
#include <cuda_runtime.h>
#include <cuda_bf16.h>
#include <cstdint>

#define N_NODES 100000
#define N_GRAPHS 2000
#define F1 64
#define F2 128
#define BN_EPS 1e-5f

// ------------------------- device scratch (no allocs allowed) ---------------
__device__ float g_deg[N_NODES];
__device__ float g_dinv[N_NODES];
__device__ float g_h1[(size_t)N_NODES * F1];
__device__ float g_out1[(size_t)N_NODES * F1];
__device__ float g_h2[(size_t)N_NODES * F2];
__device__ float g_out2[(size_t)N_NODES * F2];
__device__ float g_sum1[F1], g_sq1[F1], g_scale1[F1], g_shift1[F1];
__device__ float g_sum2[F2], g_sq2[F2], g_scale2[F2], g_shift2[F2];
__device__ float g_pool[N_GRAPHS * F2];
__device__ float g_cnt[N_GRAPHS];

// ------------------------- kernels ------------------------------------------

// Zero everything that is accumulated into (per-replay reset for graph capture).
__global__ void k_zero() {
    int i = blockIdx.x * blockDim.x + threadIdx.x;
    int stride = gridDim.x * blockDim.x;
    for (int j = i; j < N_NODES; j += stride) g_deg[j] = 0.f;
    for (int j = i; j < N_GRAPHS * F2; j += stride) g_pool[j] = 0.f;
    for (int j = i; j < N_GRAPHS; j += stride) g_cnt[j] = 0.f;
    if (i < F1) { g_sum1[i] = 0.f; g_sq1[i] = 0.f; }
    if (i < F2) { g_sum2[i] = 0.f; g_sq2[i] = 0.f; }
}

// deg[d] += 1 per edge (self loop added in k_dinv as +1).
__global__ void k_deg(const int* __restrict__ dst, int E) {
    int i = blockIdx.x * blockDim.x + threadIdx.x;
    if (i < E) atomicAdd(&g_deg[dst[i]], 1.0f);
}

__global__ void k_dinv() {
    int i = blockIdx.x * blockDim.x + threadIdx.x;
    if (i < N_NODES) g_dinv[i] = rsqrtf(g_deg[i] + 1.0f);
}

// h1 = x @ W1 ; out1 = h1 * dinv^2 (self-loop contribution as accumulator init).
// Block: 64 (features) x 4 (rows).
__global__ void k_gemm1(const float* __restrict__ x, const float* __restrict__ W1) {
    __shared__ float Ws[10 * F1];
    __shared__ float xs[4][10];
    int t = threadIdx.y * 64 + threadIdx.x;  // 0..255
    // FIX: grid-stride load — 640 weights, only 256 threads.
    for (int j = t; j < 10 * F1; j += 256) Ws[j] = W1[j];
    int row = blockIdx.x * 4 + threadIdx.y;
    if (t < 40) {
        int rr = blockIdx.x * 4 + t / 10;
        xs[t / 10][t % 10] = (rr < N_NODES) ? x[(size_t)rr * 10 + (t % 10)] : 0.f;
    }
    __syncthreads();
    if (row >= N_NODES) return;
    float acc = 0.f;
#pragma unroll
    for (int k = 0; k < 10; k++) acc += xs[threadIdx.y][k] * Ws[k * F1 + threadIdx.x];
    size_t o = (size_t)row * F1 + threadIdx.x;
    g_h1[o] = acc;
    float di = g_dinv[row];
    g_out1[o] = acc * di * di;
}

// Edge scatter, layer 1 (F=64): one warp per edge, float2 per lane, vector RED.
__global__ void k_edge1(const int* __restrict__ src, const int* __restrict__ dst, int E) {
    int gw = (blockIdx.x * blockDim.x + threadIdx.x) >> 5;
    if (gw >= E) return;
    int lane = threadIdx.x & 31;
    int s = __ldg(&src[gw]);
    int d = __ldg(&dst[gw]);
    float w = g_dinv[s] * g_dinv[d];
    const float2* hp = (const float2*)(g_h1 + (size_t)s * F1);
    float2 v = hp[lane];
    float* op = g_out1 + (size_t)d * F1 + lane * 2;
    asm volatile("red.global.add.v2.f32 [%0], {%1, %2};"
                 :: "l"(op), "f"(v.x * w), "f"(v.y * w) : "memory");
}

// Edge scatter, layer 2 (F=128): one warp per edge, float4 per lane, vector RED.
__global__ void k_edge2(const int* __restrict__ src, const int* __restrict__ dst, int E) {
    int gw = (blockIdx.x * blockDim.x + threadIdx.x) >> 5;
    if (gw >= E) return;
    int lane = threadIdx.x & 31;
    int s = __ldg(&src[gw]);
    int d = __ldg(&dst[gw]);
    float w = g_dinv[s] * g_dinv[d];
    const float4* hp = (const float4*)(g_h2 + (size_t)s * F2);
    float4 v = hp[lane];
    float* op = g_out2 + (size_t)d * F2 + lane * 4;
    asm volatile("red.global.add.v4.f32 [%0], {%1, %2, %3, %4};"
                 :: "l"(op), "f"(v.x * w), "f"(v.y * w), "f"(v.z * w), "f"(v.w * w)
                 : "memory");
}

// Per-feature sum / sum-of-squares for BN. Block = F threads, grid-stride rows.
template <int F>
__global__ void k_stats(const float* __restrict__ h, float* __restrict__ sum,
                        float* __restrict__ sq) {
    int tx = threadIdx.x;
    float s = 0.f, q = 0.f;
    for (int r = blockIdx.x; r < N_NODES; r += gridDim.x) {
        float v = h[(size_t)r * F + tx];
        s += v;
        q += v * v;
    }
    atomicAdd(&sum[tx], s);
    atomicAdd(&sq[tx], q);
}

template <int F>
__global__ void k_bnfin(const float* __restrict__ sum, const float* __restrict__ sq,
                        const float* __restrict__ gam, const float* __restrict__ bet,
                        float* __restrict__ scale, float* __restrict__ shift) {
    int tx = threadIdx.x;
    if (tx >= F) return;
    float mu = sum[tx] * (1.0f / N_NODES);
    float var = sq[tx] * (1.0f / N_NODES) - mu * mu;
    float sc = gam[tx] * rsqrtf(var + BN_EPS);
    scale[tx] = sc;
    shift[tx] = bet[tx] - mu * sc;
}

// h2 = relu(bn(out1)) @ W2 ; out2 = h2 * dinv^2.
// Block: 128 threads (one output feature each), W2 column in registers.
// Processes 2 rows per iteration from a contiguous chunk.
__global__ void __launch_bounds__(128) k_gemm2(const float* __restrict__ W2) {
    int tx = threadIdx.x;
    float w2[F1];
#pragma unroll
    for (int k = 0; k < F1; k++) w2[k] = W2[(size_t)k * F2 + tx];

    int kk = tx & 63;
    float sck = g_scale1[kk];
    float shk = g_shift1[kk];

    __shared__ float a_s[2][F1];

    int rpb = (N_NODES + gridDim.x - 1) / gridDim.x;
    int r0 = blockIdx.x * rpb;
    int r1 = min(r0 + rpb, N_NODES);
    for (int r = r0; r < r1; r += 2) {
        int lr = tx >> 6;  // 0 or 1
        int rr = r + lr;
        float v = 0.f;
        if (rr < r1) {
            v = g_out1[(size_t)rr * F1 + kk];
            v = fmaxf(v * sck + shk, 0.f);
        }
        __syncthreads();
        a_s[lr][kk] = v;
        __syncthreads();

        float acc0 = 0.f, acc1 = 0.f;
#pragma unroll
        for (int k = 0; k < F1; k++) {
            acc0 += a_s[0][k] * w2[k];
            acc1 += a_s[1][k] * w2[k];
        }
        {
            size_t o = (size_t)r * F2 + tx;
            g_h2[o] = acc0;
            float di = g_dinv[r];
            g_out2[o] = acc0 * di * di;
        }
        if (r + 1 < r1) {
            size_t o = (size_t)(r + 1) * F2 + tx;
            g_h2[o] = acc1;
            float di = g_dinv[r + 1];
            g_out2[o] = acc1 * di * di;
        }
    }
}

// Pooling: relu(bn(out2)) segment-summed by (sorted) batch id.
// Contiguous row chunk per block, register accumulate, flush on graph change.
__global__ void k_pool(const int* __restrict__ batch) {
    int tx = threadIdx.x;  // 0..127
    int rpb = (N_NODES + gridDim.x - 1) / gridDim.x;
    int r0 = blockIdx.x * rpb;
    int r1 = min(r0 + rpb, N_NODES);
    if (r0 >= r1) return;
    float sc = g_scale2[tx];
    float sh = g_shift2[tx];
    int curb = batch[r0];
    float acc = 0.f, c = 0.f;
    for (int r = r0; r < r1; r++) {
        int b = batch[r];
        if (b != curb) {
            atomicAdd(&g_pool[curb * F2 + tx], acc);
            if (tx == 0) atomicAdd(&g_cnt[curb], c);
            acc = 0.f;
            c = 0.f;
            curb = b;
        }
        float v = g_out2[(size_t)r * F2 + tx];
        acc += fmaxf(v * sc + sh, 0.f);
        c += 1.f;
    }
    atomicAdd(&g_pool[curb * F2 + tx], acc);
    if (tx == 0) atomicAdd(&g_cnt[curb], c);
}

// Final MLP head: out[g] = relu(pooled/cnt @ fW1 + fb1) @ fW2 + fb2.
// One block (64 threads) per graph.
__global__ void k_mlp(const float* __restrict__ fW1, const float* __restrict__ fb1,
                      const float* __restrict__ fW2, const float* __restrict__ fb2,
                      float* __restrict__ out) {
    int g = blockIdx.x;
    int tx = threadIdx.x;  // 0..63
    __shared__ float prow[F2];
    __shared__ float partial[2];
    float c = fmaxf(g_cnt[g], 1.0f);
    float inv = 1.0f / c;
    prow[tx] = g_pool[g * F2 + tx] * inv;
    prow[tx + 64] = g_pool[g * F2 + tx + 64] * inv;
    __syncthreads();
    float h = fb1[tx];
#pragma unroll 8
    for (int k = 0; k < F2; k++) h += prow[k] * fW1[(size_t)k * 64 + tx];
    h = fmaxf(h, 0.f);
    float p = h * fW2[tx];
#pragma unroll
    for (int off = 16; off; off >>= 1) p += __shfl_down_sync(0xffffffff, p, off);
    if ((tx & 31) == 0) partial[tx >> 5] = p;
    __syncthreads();
    if (tx == 0) out[g] = partial[0] + partial[1] + fb2[0];
}

// ------------------------- launch --------------------------------------------
extern "C" void kernel_launch(void* const* d_in, const int* in_sizes, int n_in,
                              void* d_out, int out_size) {
    const float* x   = (const float*)d_in[0];
    const int*   src = (const int*)d_in[1];
    const int*   dst = (const int*)d_in[2];
    const int*   bat = (const int*)d_in[3];
    const float* W1  = (const float*)d_in[4];
    // d_in[5] = b1 (cancels in BN), d_in[6]=g1, d_in[7]=be1
    const float* g1  = (const float*)d_in[6];
    const float* be1 = (const float*)d_in[7];
    const float* W2  = (const float*)d_in[8];
    // d_in[9] = b2 (cancels in BN)
    const float* g2  = (const float*)d_in[10];
    const float* be2 = (const float*)d_in[11];
    const float* fW1 = (const float*)d_in[12];
    const float* fb1 = (const float*)d_in[13];
    const float* fW2 = (const float*)d_in[14];
    const float* fb2 = (const float*)d_in[15];
    float* out = (float*)d_out;

    int E = in_sizes[1];

    float *p_sum1, *p_sq1, *p_scale1, *p_shift1;
    float *p_sum2, *p_sq2, *p_scale2, *p_shift2;
    cudaGetSymbolAddress((void**)&p_sum1, g_sum1);
    cudaGetSymbolAddress((void**)&p_sq1, g_sq1);
    cudaGetSymbolAddress((void**)&p_scale1, g_scale1);
    cudaGetSymbolAddress((void**)&p_shift1, g_shift1);
    cudaGetSymbolAddress((void**)&p_sum2, g_sum2);
    cudaGetSymbolAddress((void**)&p_sq2, g_sq2);
    cudaGetSymbolAddress((void**)&p_scale2, g_scale2);
    cudaGetSymbolAddress((void**)&p_shift2, g_shift2);
    float *p_out1, *p_out2;
    cudaGetSymbolAddress((void**)&p_out1, g_out1);
    cudaGetSymbolAddress((void**)&p_out2, g_out2);

    k_zero<<<512, 256>>>();
    k_deg<<<(E + 255) / 256, 256>>>(dst, E);
    k_dinv<<<(N_NODES + 255) / 256, 256>>>();
    k_gemm1<<<(N_NODES + 3) / 4, dim3(64, 4)>>>(x, W1);

    // layer 1 scatter
    {
        long long threads = (long long)E * 32;
        int blocks = (int)((threads + 255) / 256);
        k_edge1<<<blocks, 256>>>(src, dst, E);
    }
    k_stats<F1><<<1024, F1>>>(p_out1, p_sum1, p_sq1);
    k_bnfin<F1><<<1, F1>>>(p_sum1, p_sq1, g1, be1, p_scale1, p_shift1);

    k_gemm2<<<2048, 128>>>(W2);

    // layer 2 scatter
    {
        long long threads = (long long)E * 32;
        int blocks = (int)((threads + 255) / 256);
        k_edge2<<<blocks, 256>>>(src, dst, E);
    }
    k_stats<F2><<<1024, F2>>>(p_out2, p_sum2, p_sq2);
    k_bnfin<F2><<<1, F2>>>(p_sum2, p_sq2, g2, be2, p_scale2, p_shift2);

    k_pool<<<1024, 128>>>(bat);
    k_mlp<<<N_GRAPHS, 64>>>(fW1, fb1, fW2, fb2, out);
}

// round 3
// speedup vs baseline: 1.7065x; 1.7065x over previous
#include <cuda_runtime.h>
#include <cuda_bf16.h>
#include <cstdint>

#define N_NODES 100000
#define N_GRAPHS 2000
#define E_MAX 3200000
#define F1 64
#define F2 128
#define BN_EPS 1e-5f

// ------------------------- device scratch (no allocs allowed) ---------------
__device__ int   g_degi[N_NODES];
__device__ int   g_rowptr[N_NODES + 1];
__device__ int   g_cursor[N_NODES];
__device__ int   g_srcsorted[E_MAX];
__device__ float g_dinv[N_NODES];
__device__ float g_h1s[(size_t)N_NODES * F1];   // h1 * dinv
__device__ float g_out1[(size_t)N_NODES * F1];
__device__ float g_h2s[(size_t)N_NODES * F2];   // h2 * dinv
__device__ float g_out2[(size_t)N_NODES * F2];
__device__ float g_sum1[F1], g_sq1[F1], g_scale1[F1], g_shift1[F1];
__device__ float g_sum2[F2], g_sq2[F2], g_scale2[F2], g_shift2[F2];
__device__ float g_pool[N_GRAPHS * F2];
__device__ float g_cnt[N_GRAPHS];

// ------------------------- kernels ------------------------------------------

// Zero accumulators (per-replay reset; graph-capturable).
__global__ void k_zero() {
    int i = blockIdx.x * blockDim.x + threadIdx.x;
    int stride = gridDim.x * blockDim.x;
    for (int j = i; j < N_NODES; j += stride) g_degi[j] = 0;
    for (int j = i; j < N_GRAPHS * F2; j += stride) g_pool[j] = 0.f;
    for (int j = i; j < N_GRAPHS; j += stride) g_cnt[j] = 0.f;
    if (i < F1) { g_sum1[i] = 0.f; g_sq1[i] = 0.f; }
    if (i < F2) { g_sum2[i] = 0.f; g_sq2[i] = 0.f; }
}

// In-degree histogram.
__global__ void k_hist(const int* __restrict__ dst, int E) {
    int i = blockIdx.x * blockDim.x + threadIdx.x;
    if (i < E) atomicAdd(&g_degi[dst[i]], 1);
}

// Single-block exclusive scan of g_degi -> g_rowptr (and g_cursor copy).
#define SCAN_T 1024
__global__ void __launch_bounds__(SCAN_T) k_scan() {
    __shared__ int wsum[32];
    int tid = threadIdx.x;
    int lane = tid & 31, wid = tid >> 5;
    const int chunk = (N_NODES + SCAN_T - 1) / SCAN_T;
    int start = tid * chunk;
    int end = min(start + chunk, N_NODES);
    int s = 0;
    for (int i = start; i < end; i++) s += g_degi[i];
    int v = s;
#pragma unroll
    for (int o = 1; o < 32; o <<= 1) {
        int t = __shfl_up_sync(0xffffffffu, v, o);
        if (lane >= o) v += t;
    }
    if (lane == 31) wsum[wid] = v;
    __syncthreads();
    if (wid == 0) {
        int w = wsum[lane];
#pragma unroll
        for (int o = 1; o < 32; o <<= 1) {
            int t = __shfl_up_sync(0xffffffffu, w, o);
            if (lane >= o) w += t;
        }
        wsum[lane] = w;
    }
    __syncthreads();
    int excl = v - s + (wid > 0 ? wsum[wid - 1] : 0);
    int run = excl;
    for (int i = start; i < end; i++) {
        g_rowptr[i] = run;
        g_cursor[i] = run;
        run += g_degi[i];
    }
    if (tid == SCAN_T - 1) g_rowptr[N_NODES] = run;
}

__global__ void k_dinv() {
    int i = blockIdx.x * blockDim.x + threadIdx.x;
    if (i < N_NODES) g_dinv[i] = rsqrtf((float)g_degi[i] + 1.0f);
}

// Bucket edges by dst: sorted src index list per row.
__global__ void k_fill(const int* __restrict__ src, const int* __restrict__ dst, int E) {
    int i = blockIdx.x * blockDim.x + threadIdx.x;
    if (i >= E) return;
    int p = atomicAdd(&g_cursor[dst[i]], 1);
    g_srcsorted[p] = src[i];
}

// h1s = (x @ W1) * dinv.  Block: 64 (features) x 4 (rows).
__global__ void k_gemm1(const float* __restrict__ x, const float* __restrict__ W1) {
    __shared__ float Ws[10 * F1];
    __shared__ float xs[4][10];
    int t = threadIdx.y * 64 + threadIdx.x;  // 0..255
    for (int j = t; j < 10 * F1; j += 256) Ws[j] = W1[j];
    int row = blockIdx.x * 4 + threadIdx.y;
    if (t < 40) {
        int rr = blockIdx.x * 4 + t / 10;
        xs[t / 10][t % 10] = (rr < N_NODES) ? x[(size_t)rr * 10 + (t % 10)] : 0.f;
    }
    __syncthreads();
    if (row >= N_NODES) return;
    float acc = 0.f;
#pragma unroll
    for (int k = 0; k < 10; k++) acc += xs[threadIdx.y][k] * Ws[k * F1 + threadIdx.x];
    g_h1s[(size_t)row * F1 + threadIdx.x] = acc * g_dinv[row];
}

// CSR aggregate, layer 1 (F=64, float2/lane). One warp per row.
// out1[d] = dinv[d] * (h1s[d] + sum_{s in nbr(d)} h1s[s]); fused BN sum/sumsq.
__global__ void __launch_bounds__(256) k_csr64() {
    __shared__ float s_sum[F1], s_sq[F1];
    int tid = threadIdx.x;
    if (tid < F1) { s_sum[tid] = 0.f; s_sq[tid] = 0.f; }
    __syncthreads();
    int lane = tid & 31;
    int gw = (blockIdx.x * blockDim.x + tid) >> 5;
    int nw = (gridDim.x * blockDim.x) >> 5;
    float ls0 = 0.f, ls1 = 0.f, lq0 = 0.f, lq1 = 0.f;
    for (int row = gw; row < N_NODES; row += nw) {
        int beg = g_rowptr[row];
        int endp = g_rowptr[row + 1];
        float2 acc = *(const float2*)(g_h1s + (size_t)row * F1 + lane * 2);
        int e = beg;
        while (e < endp) {
            int n = min(32, endp - e);
            int myidx = (lane < n) ? g_srcsorted[e + lane] : 0;
            e += n;
            int j = 0;
            for (; j + 4 <= n; j += 4) {
                int s0 = __shfl_sync(0xffffffffu, myidx, j);
                int s1 = __shfl_sync(0xffffffffu, myidx, j + 1);
                int s2 = __shfl_sync(0xffffffffu, myidx, j + 2);
                int s3 = __shfl_sync(0xffffffffu, myidx, j + 3);
                float2 v0 = *(const float2*)(g_h1s + (size_t)s0 * F1 + lane * 2);
                float2 v1 = *(const float2*)(g_h1s + (size_t)s1 * F1 + lane * 2);
                float2 v2 = *(const float2*)(g_h1s + (size_t)s2 * F1 + lane * 2);
                float2 v3 = *(const float2*)(g_h1s + (size_t)s3 * F1 + lane * 2);
                acc.x += (v0.x + v1.x) + (v2.x + v3.x);
                acc.y += (v0.y + v1.y) + (v2.y + v3.y);
            }
            for (; j < n; j++) {
                int s0 = __shfl_sync(0xffffffffu, myidx, j);
                float2 v0 = *(const float2*)(g_h1s + (size_t)s0 * F1 + lane * 2);
                acc.x += v0.x;
                acc.y += v0.y;
            }
        }
        float di = g_dinv[row];
        float o0 = acc.x * di, o1 = acc.y * di;
        *(float2*)(g_out1 + (size_t)row * F1 + lane * 2) = make_float2(o0, o1);
        ls0 += o0; ls1 += o1;
        lq0 += o0 * o0; lq1 += o1 * o1;
    }
    atomicAdd(&s_sum[lane * 2 + 0], ls0);
    atomicAdd(&s_sum[lane * 2 + 1], ls1);
    atomicAdd(&s_sq[lane * 2 + 0], lq0);
    atomicAdd(&s_sq[lane * 2 + 1], lq1);
    __syncthreads();
    if (tid < F1) {
        atomicAdd(&g_sum1[tid], s_sum[tid]);
        atomicAdd(&g_sq1[tid], s_sq[tid]);
    }
}

// CSR aggregate, layer 2 (F=128, float4/lane). One warp per row. Fused BN stats.
__global__ void __launch_bounds__(256) k_csr128() {
    __shared__ float s_sum[F2], s_sq[F2];
    int tid = threadIdx.x;
    if (tid < F2) { s_sum[tid] = 0.f; s_sq[tid] = 0.f; }
    __syncthreads();
    int lane = tid & 31;
    int gw = (blockIdx.x * blockDim.x + tid) >> 5;
    int nw = (gridDim.x * blockDim.x) >> 5;
    float ls[4] = {0.f, 0.f, 0.f, 0.f};
    float lq[4] = {0.f, 0.f, 0.f, 0.f};
    for (int row = gw; row < N_NODES; row += nw) {
        int beg = g_rowptr[row];
        int endp = g_rowptr[row + 1];
        float4 acc = *(const float4*)(g_h2s + (size_t)row * F2 + lane * 4);
        int e = beg;
        while (e < endp) {
            int n = min(32, endp - e);
            int myidx = (lane < n) ? g_srcsorted[e + lane] : 0;
            e += n;
            int j = 0;
            for (; j + 4 <= n; j += 4) {
                int s0 = __shfl_sync(0xffffffffu, myidx, j);
                int s1 = __shfl_sync(0xffffffffu, myidx, j + 1);
                int s2 = __shfl_sync(0xffffffffu, myidx, j + 2);
                int s3 = __shfl_sync(0xffffffffu, myidx, j + 3);
                float4 v0 = *(const float4*)(g_h2s + (size_t)s0 * F2 + lane * 4);
                float4 v1 = *(const float4*)(g_h2s + (size_t)s1 * F2 + lane * 4);
                float4 v2 = *(const float4*)(g_h2s + (size_t)s2 * F2 + lane * 4);
                float4 v3 = *(const float4*)(g_h2s + (size_t)s3 * F2 + lane * 4);
                acc.x += (v0.x + v1.x) + (v2.x + v3.x);
                acc.y += (v0.y + v1.y) + (v2.y + v3.y);
                acc.z += (v0.z + v1.z) + (v2.z + v3.z);
                acc.w += (v0.w + v1.w) + (v2.w + v3.w);
            }
            for (; j < n; j++) {
                int s0 = __shfl_sync(0xffffffffu, myidx, j);
                float4 v0 = *(const float4*)(g_h2s + (size_t)s0 * F2 + lane * 4);
                acc.x += v0.x; acc.y += v0.y; acc.z += v0.z; acc.w += v0.w;
            }
        }
        float di = g_dinv[row];
        float4 o;
        o.x = acc.x * di; o.y = acc.y * di; o.z = acc.z * di; o.w = acc.w * di;
        *(float4*)(g_out2 + (size_t)row * F2 + lane * 4) = o;
        ls[0] += o.x; ls[1] += o.y; ls[2] += o.z; ls[3] += o.w;
        lq[0] += o.x * o.x; lq[1] += o.y * o.y; lq[2] += o.z * o.z; lq[3] += o.w * o.w;
    }
#pragma unroll
    for (int j = 0; j < 4; j++) {
        atomicAdd(&s_sum[lane * 4 + j], ls[j]);
        atomicAdd(&s_sq[lane * 4 + j], lq[j]);
    }
    __syncthreads();
    if (tid < F2) {
        atomicAdd(&g_sum2[tid], s_sum[tid]);
        atomicAdd(&g_sq2[tid], s_sq[tid]);
    }
}

template <int F>
__global__ void k_bnfin(const float* __restrict__ sum, const float* __restrict__ sq,
                        const float* __restrict__ gam, const float* __restrict__ bet,
                        float* __restrict__ scale, float* __restrict__ shift) {
    int tx = threadIdx.x;
    if (tx >= F) return;
    float mu = sum[tx] * (1.0f / N_NODES);
    float var = sq[tx] * (1.0f / N_NODES) - mu * mu;
    float sc = gam[tx] * rsqrtf(var + BN_EPS);
    scale[tx] = sc;
    shift[tx] = bet[tx] - mu * sc;
}

// h2s = (relu(bn(out1)) @ W2) * dinv.  Block: 128 threads.
__global__ void __launch_bounds__(128) k_gemm2(const float* __restrict__ W2) {
    int tx = threadIdx.x;
    float w2[F1];
#pragma unroll
    for (int k = 0; k < F1; k++) w2[k] = W2[(size_t)k * F2 + tx];

    int kk = tx & 63;
    float sck = g_scale1[kk];
    float shk = g_shift1[kk];

    __shared__ float a_s[2][F1];

    int rpb = (N_NODES + gridDim.x - 1) / gridDim.x;
    int r0 = blockIdx.x * rpb;
    int r1 = min(r0 + rpb, N_NODES);
    for (int r = r0; r < r1; r += 2) {
        int lr = tx >> 6;
        int rr = r + lr;
        float v = 0.f;
        if (rr < r1) {
            v = g_out1[(size_t)rr * F1 + kk];
            v = fmaxf(v * sck + shk, 0.f);
        }
        __syncthreads();
        a_s[lr][kk] = v;
        __syncthreads();

        float acc0 = 0.f, acc1 = 0.f;
#pragma unroll
        for (int k = 0; k < F1; k++) {
            acc0 += a_s[0][k] * w2[k];
            acc1 += a_s[1][k] * w2[k];
        }
        g_h2s[(size_t)r * F2 + tx] = acc0 * g_dinv[r];
        if (r + 1 < r1)
            g_h2s[(size_t)(r + 1) * F2 + tx] = acc1 * g_dinv[r + 1];
    }
}

// Pooling: relu(bn(out2)) segment-summed by sorted batch id.
__global__ void k_pool(const int* __restrict__ batch) {
    int tx = threadIdx.x;  // 0..127
    int rpb = (N_NODES + gridDim.x - 1) / gridDim.x;
    int r0 = blockIdx.x * rpb;
    int r1 = min(r0 + rpb, N_NODES);
    if (r0 >= r1) return;
    float sc = g_scale2[tx];
    float sh = g_shift2[tx];
    int curb = batch[r0];
    float acc = 0.f, c = 0.f;
    for (int r = r0; r < r1; r++) {
        int b = batch[r];
        if (b != curb) {
            atomicAdd(&g_pool[curb * F2 + tx], acc);
            if (tx == 0) atomicAdd(&g_cnt[curb], c);
            acc = 0.f; c = 0.f;
            curb = b;
        }
        float v = g_out2[(size_t)r * F2 + tx];
        acc += fmaxf(v * sc + sh, 0.f);
        c += 1.f;
    }
    atomicAdd(&g_pool[curb * F2 + tx], acc);
    if (tx == 0) atomicAdd(&g_cnt[curb], c);
}

// Final MLP head. One block (64 threads) per graph.
__global__ void k_mlp(const float* __restrict__ fW1, const float* __restrict__ fb1,
                      const float* __restrict__ fW2, const float* __restrict__ fb2,
                      float* __restrict__ out) {
    int g = blockIdx.x;
    int tx = threadIdx.x;  // 0..63
    __shared__ float prow[F2];
    __shared__ float partial[2];
    float c = fmaxf(g_cnt[g], 1.0f);
    float inv = 1.0f / c;
    prow[tx] = g_pool[g * F2 + tx] * inv;
    prow[tx + 64] = g_pool[g * F2 + tx + 64] * inv;
    __syncthreads();
    float h = fb1[tx];
#pragma unroll 8
    for (int k = 0; k < F2; k++) h += prow[k] * fW1[(size_t)k * 64 + tx];
    h = fmaxf(h, 0.f);
    float p = h * fW2[tx];
#pragma unroll
    for (int off = 16; off; off >>= 1) p += __shfl_down_sync(0xffffffff, p, off);
    if ((tx & 31) == 0) partial[tx >> 5] = p;
    __syncthreads();
    if (tx == 0) out[g] = partial[0] + partial[1] + fb2[0];
}

// ------------------------- launch --------------------------------------------
extern "C" void kernel_launch(void* const* d_in, const int* in_sizes, int n_in,
                              void* d_out, int out_size) {
    const float* x   = (const float*)d_in[0];
    const int*   src = (const int*)d_in[1];
    const int*   dst = (const int*)d_in[2];
    const int*   bat = (const int*)d_in[3];
    const float* W1  = (const float*)d_in[4];
    // d_in[5] = b1 (cancels in BN)
    const float* g1  = (const float*)d_in[6];
    const float* be1 = (const float*)d_in[7];
    const float* W2  = (const float*)d_in[8];
    // d_in[9] = b2 (cancels in BN)
    const float* g2  = (const float*)d_in[10];
    const float* be2 = (const float*)d_in[11];
    const float* fW1 = (const float*)d_in[12];
    const float* fb1 = (const float*)d_in[13];
    const float* fW2 = (const float*)d_in[14];
    const float* fb2 = (const float*)d_in[15];
    float* out = (float*)d_out;

    int E = in_sizes[1];

    float *p_sum1, *p_sq1, *p_scale1, *p_shift1;
    float *p_sum2, *p_sq2, *p_scale2, *p_shift2;
    cudaGetSymbolAddress((void**)&p_sum1, g_sum1);
    cudaGetSymbolAddress((void**)&p_sq1, g_sq1);
    cudaGetSymbolAddress((void**)&p_scale1, g_scale1);
    cudaGetSymbolAddress((void**)&p_shift1, g_shift1);
    cudaGetSymbolAddress((void**)&p_sum2, g_sum2);
    cudaGetSymbolAddress((void**)&p_sq2, g_sq2);
    cudaGetSymbolAddress((void**)&p_scale2, g_scale2);
    cudaGetSymbolAddress((void**)&p_shift2, g_shift2);

    k_zero<<<512, 256>>>();
    k_hist<<<(E + 255) / 256, 256>>>(dst, E);
    k_scan<<<1, SCAN_T>>>();
    k_dinv<<<(N_NODES + 255) / 256, 256>>>();
    k_fill<<<(E + 255) / 256, 256>>>(src, dst, E);

    k_gemm1<<<(N_NODES + 3) / 4, dim3(64, 4)>>>(x, W1);
    k_csr64<<<2048, 256>>>();
    k_bnfin<F1><<<1, F1>>>(p_sum1, p_sq1, g1, be1, p_scale1, p_shift1);

    k_gemm2<<<2048, 128>>>(W2);
    k_csr128<<<2048, 256>>>();
    k_bnfin<F2><<<1, F2>>>(p_sum2, p_sq2, g2, be2, p_scale2, p_shift2);

    k_pool<<<1024, 128>>>(bat);
    k_mlp<<<N_GRAPHS, 64>>>(fW1, fb1, fW2, fb2, out);
}